// round 13
// baseline (speedup 1.0000x reference)
#include <cuda_runtime.h>
#include <cuda_fp16.h>
#include <cstdint>

#define NN 50000
#define NE 100000

// ---------------- persistent device scratch ----------------
__device__ float  g_x[NN * 64];
__device__ float  g_agg[NN * 64];
__device__ float  g_ehT[(size_t)64 * NE];     // edge hidden, transposed [h][e]
__device__ __half g_b2h[64 * 4096];           // permuted We2 hi: [o][h*64+j]
__device__ __half g_b2l[64 * 4096];           // permuted We2 lo
__device__ __half g_bm_h[64 * 64];            // be2 as matrix, hi
__device__ __half g_bm_l[64 * 64];            // be2 as matrix, lo
__device__ __half g_wih_h[192 * 64];
__device__ __half g_wih_l[192 * 64];
__device__ __half g_whh_h[192 * 64];
__device__ __half g_whh_l[192 * 64];
__device__ float  g_gi[(size_t)NN * 192];
__device__ float  g_gh[(size_t)NN * 192];

__device__ __forceinline__ uint32_t smem_u32(const void* p) {
    uint32_t a;
    asm("{ .reg .u64 t; cvta.to.shared.u64 t, %1; cvt.u32.u64 %0, t; }" : "=r"(a) : "l"(p));
    return a;
}

#define MMA_ACC(d, a, b0, b1)                                             \
    asm volatile(                                                         \
        "mma.sync.aligned.m16n8k16.row.col.f32.f16.f16.f32 "              \
        "{%0,%1,%2,%3},{%4,%5,%6,%7},{%8,%9},{%0,%1,%2,%3};"              \
        : "+f"((d)[0]), "+f"((d)[1]), "+f"((d)[2]), "+f"((d)[3])          \
        : "r"((a)[0]), "r"((a)[1]), "r"((a)[2]), "r"((a)[3]),             \
          "r"(b0), "r"(b1))

#define MMA_NEW(d, a, b0, b1, z)                                          \
    asm volatile(                                                         \
        "mma.sync.aligned.m16n8k16.row.col.f32.f16.f16.f32 "              \
        "{%0,%1,%2,%3},{%4,%5,%6,%7},{%8,%9},{%10,%10,%10,%10};"          \
        : "=f"((d)[0]), "=f"((d)[1]), "=f"((d)[2]), "=f"((d)[3])          \
        : "r"((a)[0]), "r"((a)[1]), "r"((a)[2]), "r"((a)[3]),             \
          "r"(b0), "r"(b1), "f"(z))

#define LDSM4(r0, r1, r2, r3, addr)                                       \
    asm volatile("ldmatrix.sync.aligned.m8n8.x4.shared.b16 {%0,%1,%2,%3}, [%4];" \
        : "=r"(r0), "=r"(r1), "=r"(r2), "=r"(r3) : "r"(addr))

#define CP16(dst, src) \
    asm volatile("cp.async.cg.shared.global [%0], [%1], 16;" :: "r"(dst), "l"(src))
#define CPCOMMIT() asm volatile("cp.async.commit_group;")
#define CPWAIT0()  asm volatile("cp.async.wait_group 0;")

// ---------------- x0 = NF @ Win^T + bin (fp32) ----------------
__global__ void __launch_bounds__(256) k_x0(const float* __restrict__ nf,
                                            const float* __restrict__ Win,
                                            const float* __restrict__ bin) {
    __shared__ float w[1024];
    __shared__ float b[64];
    int tid = threadIdx.x;
    for (int i = tid; i < 1024; i += 256) w[i] = Win[i];
    if (tid < 64) b[tid] = bin[tid];
    __syncthreads();
    int idx = blockIdx.x * 256 + tid;
    if (idx >= NN * 64) return;
    int v = idx >> 6, h = idx & 63;
    const float* row = nf + (size_t)v * 16;
    float acc = b[h];
#pragma unroll
    for (int k = 0; k < 16; k++) acc += row[k] * w[h * 16 + k];
    g_x[idx] = acc;
}

// ---------------- eh = relu(EF @ We1^T + be1), stored transposed fp32 ----------------
__global__ void __launch_bounds__(256) k_edge_mlp(const float* __restrict__ ef,
                                                  const float* __restrict__ We1,
                                                  const float* __restrict__ be1) {
    __shared__ float w[512];
    __shared__ float b[64];
    __shared__ float efs[64 * 8];
    __shared__ float tile[64 * 65];
    int tid = threadIdx.x;
    for (int i = tid; i < 512; i += 256) w[i] = We1[i];
    if (tid < 64) b[tid] = be1[tid];
    int e0 = blockIdx.x * 64;
    for (int i = tid; i < 512; i += 256) {
        int el = i >> 3, k = i & 7;
        efs[i] = (e0 + el < NE) ? ef[(size_t)(e0 + el) * 8 + k] : 0.f;
    }
    __syncthreads();
#pragma unroll
    for (int t = 0; t < 16; t++) {
        int idx = tid + 256 * t;
        int el = idx >> 6, h = idx & 63;
        float acc = b[h];
#pragma unroll
        for (int k = 0; k < 8; k++) acc += efs[el * 8 + k] * w[h * 8 + k];
        tile[el * 65 + h] = fmaxf(acc, 0.f);
    }
    __syncthreads();
#pragma unroll
    for (int t = 0; t < 16; t++) {
        int idx = tid + 256 * t;
        int h = idx >> 6, el = idx & 63;
        if (e0 + el < NE) g_ehT[(size_t)h * NE + e0 + el] = tile[el * 65 + h];
    }
}

// ---------------- weight preparation: permute + hi/lo fp16 split ----------------
__global__ void __launch_bounds__(256) k_prep(const float* __restrict__ We2,
                                              const float* __restrict__ Wih,
                                              const float* __restrict__ Whh,
                                              const float* __restrict__ be2) {
    int i = blockIdx.x * 256 + threadIdx.x;
    if (i < 262144) {
        int o = i >> 12;
        int k = i & 4095;
        int h = k >> 6, j = k & 63;
        float v = We2[(size_t)(o * 64 + j) * 64 + h];
        __half hi = __float2half_rn(v);
        g_b2h[i] = hi;
        g_b2l[i] = __float2half_rn(v - __half2float(hi));
    } else if (i < 262144 + 12288) {
        int t = i - 262144;
        float v = Wih[t];
        __half hi = __float2half_rn(v);
        g_wih_h[t] = hi;
        g_wih_l[t] = __float2half_rn(v - __half2float(hi));
    } else if (i < 262144 + 24576) {
        int t = i - 274432;
        float v = Whh[t];
        __half hi = __float2half_rn(v);
        g_whh_h[t] = hi;
        g_whh_l[t] = __float2half_rn(v - __half2float(hi));
    } else if (i < 262144 + 24576 + 4096) {
        int t = i - 286720;
        float v = be2[t];
        __half hi = __float2half_rn(v);
        g_bm_h[t] = hi;
        g_bm_l[t] = __float2half_rn(v - __half2float(hi));
    }
}

// ---------------- fused message GEMM (round-9/10 proven: ~411 us/step) ----------------
#define MSG_SMEM 74752

__global__ void __launch_bounds__(256, 2) k_msg(const int* __restrict__ esrc,
                                                const int* __restrict__ etgt) {
    extern __shared__ char smc[];
    uint32_t base = smem_u32(smc);
    int* sc = (int*)(smc + 73728);
    int* tg = (int*)(smc + 74240);

    int tid = threadIdx.x, lane = tid & 31, wid = tid >> 5;
    int e0 = blockIdx.x * 128;
    int nEl = NE - e0; if (nEl > 128) nEl = 128;

#define COPY_B(v, d) do {                                                       \
        const __half* _sh; const __half* _sl; size_t _st;                       \
        if ((v) < 64) { _sh = g_b2h + (size_t)(v) * 64;                         \
                        _sl = g_b2l + (size_t)(v) * 64; _st = 4096; }           \
        else          { _sh = g_bm_h; _sl = g_bm_l; _st = 64; }                 \
        _Pragma("unroll")                                                       \
        for (int _i = 0; _i < 2; _i++) {                                        \
            int _id = tid + 256 * _i;                                           \
            int _row = _id >> 3, _q = _id & 7;                                  \
            uint32_t _dh = base + 36864 + (uint32_t)(d) * 9216 + _row * 144 + _q * 16; \
            CP16(_dh, _sh + (size_t)_row * _st + _q * 8);                       \
            CP16(_dh + 18432, _sl + (size_t)_row * _st + _q * 8);               \
        }                                                                       \
        CPCOMMIT();                                                             \
    } while (0)

    COPY_B(0, 0);

    if (tid < 128) {
        sc[tid] = (tid < nEl) ? esrc[e0 + tid] : 0;
        tg[tid] = (tid < nEl) ? etgt[e0 + tid] : 0;
    }
    __syncthreads();

    __half* XH = (__half*)smc;
    __half* XL = (__half*)(smc + 18432);
#pragma unroll
    for (int i = 0; i < 32; i++) {
        int idx = tid + 256 * i;
        int row = idx >> 6, j = idx & 63;
        float v = g_x[(size_t)sc[row] * 64 + j];
        __half hi = __float2half_rn(v);
        XH[row * 72 + j] = hi;
        XL[row * 72 + j] = __float2half_rn(v - __half2float(hi));
    }

    int wm = (wid >> 1) * 32, wn = (wid & 1) * 32;
    int r = lane >> 2, kq = (lane & 3) * 2;

    uint32_t aOff = (uint32_t)(wm + (lane & 15)) * 144 + (uint32_t)(lane >> 4) * 16;
    uint32_t aHiB = base + aOff;
    uint32_t bOff0 = (uint32_t)(wn + (lane & 7) + ((lane & 16) >> 1)) * 144 + ((uint32_t)(lane & 8) << 1);
    uint32_t bOff1 = bOff0 + 16 * 144;

    float acc[2][4][4];
#pragma unroll
    for (int a = 0; a < 2; a++)
#pragma unroll
        for (int b = 0; b < 4; b++)
#pragma unroll
            for (int c = 0; c < 4; c++) acc[a][b][c] = 0.f;

    float fz = 0.f;

    int er0 = wm + r, er1 = wm + 8 + r, er2 = wm + 16 + r, er3 = wm + 24 + r;
#define LD_EH(dst, u) do {                                                      \
        if ((u) < 64) {                                                         \
            const float* _p = g_ehT + (size_t)(u) * NE + e0;                    \
            (dst).x = (er0 < nEl) ? __ldg(_p + er0) : 0.f;                      \
            (dst).y = (er1 < nEl) ? __ldg(_p + er1) : 0.f;                      \
            (dst).z = (er2 < nEl) ? __ldg(_p + er2) : 0.f;                      \
            (dst).w = (er3 < nEl) ? __ldg(_p + er3) : 0.f;                      \
        } else { (dst).x = 1.f; (dst).y = 1.f; (dst).z = 1.f; (dst).w = 1.f; }  \
    } while (0)

    float4 ehc, ehn;
    LD_EH(ehc, 0);

    for (int u = 0; u <= 64; u++) {
        int b = u & 1;
        CPWAIT0();
        __syncthreads();
        if (u < 64) COPY_B(u + 1, b ^ 1);
        if (u < 64) LD_EH(ehn, u + 1);

        uint32_t bhB = base + 36864 + (uint32_t)b * 9216;

        float tmp[2][4][4];
#pragma unroll
        for (int kk = 0; kk < 4; kk++) {
            uint32_t ah[2][4], al[2][4], bh[2][4], bl[2][4];
#pragma unroll
            for (int mf = 0; mf < 2; mf++) {
                uint32_t aa = aHiB + (uint32_t)mf * 2304 + (uint32_t)kk * 32;
                LDSM4(ah[mf][0], ah[mf][1], ah[mf][2], ah[mf][3], aa);
                LDSM4(al[mf][0], al[mf][1], al[mf][2], al[mf][3], aa + 18432);
            }
            {
                uint32_t ba0 = bhB + bOff0 + (uint32_t)kk * 32;
                uint32_t ba1 = bhB + bOff1 + (uint32_t)kk * 32;
                LDSM4(bh[0][0], bh[0][1], bh[0][2], bh[0][3], ba0);
                LDSM4(bh[1][0], bh[1][1], bh[1][2], bh[1][3], ba1);
                LDSM4(bl[0][0], bl[0][1], bl[0][2], bl[0][3], ba0 + 18432);
                LDSM4(bl[1][0], bl[1][1], bl[1][2], bl[1][3], ba1 + 18432);
            }
#pragma unroll
            for (int nf = 0; nf < 4; nf++) {
                int np = nf >> 1, o = (nf & 1) * 2;
                uint32_t b0 = bh[np][o], b1 = bh[np][o + 1];
                uint32_t c0 = bl[np][o], c1 = bl[np][o + 1];
#pragma unroll
                for (int mf = 0; mf < 2; mf++) {
                    if (kk == 0) { MMA_NEW(tmp[mf][nf], ah[mf], b0, b1, fz); }
                    else         { MMA_ACC(tmp[mf][nf], ah[mf], b0, b1); }
                    MMA_ACC(tmp[mf][nf], al[mf], b0, b1);
                    MMA_ACC(tmp[mf][nf], ah[mf], c0, c1);
                }
            }
        }
#pragma unroll
        for (int nf = 0; nf < 4; nf++) {
            acc[0][nf][0] += ehc.x * tmp[0][nf][0];
            acc[0][nf][1] += ehc.x * tmp[0][nf][1];
            acc[0][nf][2] += ehc.y * tmp[0][nf][2];
            acc[0][nf][3] += ehc.y * tmp[0][nf][3];
            acc[1][nf][0] += ehc.z * tmp[1][nf][0];
            acc[1][nf][1] += ehc.z * tmp[1][nf][1];
            acc[1][nf][2] += ehc.w * tmp[1][nf][2];
            acc[1][nf][3] += ehc.w * tmp[1][nf][3];
        }
        ehc = ehn;
    }

#pragma unroll
    for (int mf = 0; mf < 2; mf++) {
        int rl = wm + mf * 16 + r;
#pragma unroll
        for (int nf = 0; nf < 4; nf++) {
            int c = wn + nf * 8 + kq;
            if (rl < nEl) {
                float* ap = g_agg + (size_t)tg[rl] * 64 + c;
                atomicAdd(ap,     acc[mf][nf][0]);
                atomicAdd(ap + 1, acc[mf][nf][1]);
            }
            if (rl + 8 < nEl) {
                float* ap = g_agg + (size_t)tg[rl + 8] * 64 + c;
                atomicAdd(ap,     acc[mf][nf][2]);
                atomicAdd(ap + 1, acc[mf][nf][3]);
            }
        }
    }
#undef COPY_B
#undef LD_EH
}

// ---------------- fused GRU GEMM: y=0: gi=agg@Wih^T (and zero agg), y=1: gh=x@Whh^T ----
__global__ void __launch_bounds__(256) gemm_gru(const float* __restrict__ Aagg,
                                                const float* __restrict__ Ax) {
    extern __shared__ char smc[];
    __half* ash = (__half*)smc;           // [128][72]
    __half* asl = ash + 128 * 72;
    __half* bsh = asl + 128 * 72;         // [64][72]
    __half* bsl = bsh + 64 * 72;

    const float* A   = blockIdx.y ? Ax : Aagg;
    const __half* BhAll = blockIdx.y ? g_whh_h : g_wih_h;
    const __half* BlAll = blockIdx.y ? g_whh_l : g_wih_l;
    float* C         = blockIdx.y ? g_gh : g_gi;

    int tid = threadIdx.x, lane = tid & 31, wid = tid >> 5;
    int m0 = blockIdx.x * 128;
    int M = NN;

#pragma unroll
    for (int i = 0; i < 32; i++) {
        int idx = tid + 256 * i;
        int rr = idx >> 6, j = idx & 63;
        float v = 0.f;
        if (m0 + rr < M) {
            v = A[(size_t)(m0 + rr) * 64 + j];
            if (blockIdx.y == 0) g_agg[(size_t)(m0 + rr) * 64 + j] = 0.f;  // fold memset
        }
        __half hi = __float2half_rn(v);
        ash[rr * 72 + j] = hi;
        asl[rr * 72 + j] = __float2half_rn(v - __half2float(hi));
    }

    int wm = (wid >> 1) * 32, wn = (wid & 1) * 32;
    int r = lane >> 2, kq = (lane & 3) * 2;

    for (int nc = 0; nc < 3; nc++) {
        int n0 = nc * 64;
        __syncthreads();   // A ready (nc=0) / previous-chunk MMAs done (nc>0)
#pragma unroll
        for (int i = 0; i < 2; i++) {
            int id2 = tid + 256 * i;
            int row = id2 >> 3, q = id2 & 7;
            *(uint4*)(bsh + row * 72 + q * 8) = *(const uint4*)(BhAll + (size_t)(n0 + row) * 64 + q * 8);
            *(uint4*)(bsl + row * 72 + q * 8) = *(const uint4*)(BlAll + (size_t)(n0 + row) * 64 + q * 8);
        }
        __syncthreads();

        float acc[2][4][4];
#pragma unroll
        for (int a = 0; a < 2; a++)
#pragma unroll
            for (int b = 0; b < 4; b++)
#pragma unroll
                for (int c = 0; c < 4; c++) acc[a][b][c] = 0.f;

#pragma unroll
        for (int kk = 0; kk < 4; kk++) {
            int k0 = kk * 16 + kq;
            unsigned Ahi[2][4], Alo[2][4];
#pragma unroll
            for (int mf = 0; mf < 2; mf++) {
                int rr = wm + mf * 16 + r;
                Ahi[mf][0] = *(const unsigned*)(ash + rr * 72 + k0);
                Ahi[mf][1] = *(const unsigned*)(ash + (rr + 8) * 72 + k0);
                Ahi[mf][2] = *(const unsigned*)(ash + rr * 72 + k0 + 8);
                Ahi[mf][3] = *(const unsigned*)(ash + (rr + 8) * 72 + k0 + 8);
                Alo[mf][0] = *(const unsigned*)(asl + rr * 72 + k0);
                Alo[mf][1] = *(const unsigned*)(asl + (rr + 8) * 72 + k0);
                Alo[mf][2] = *(const unsigned*)(asl + rr * 72 + k0 + 8);
                Alo[mf][3] = *(const unsigned*)(asl + (rr + 8) * 72 + k0 + 8);
            }
#pragma unroll
            for (int nf = 0; nf < 4; nf++) {
                int nn = wn + nf * 8 + r;
                unsigned b0 = *(const unsigned*)(bsh + nn * 72 + k0);
                unsigned b1 = *(const unsigned*)(bsh + nn * 72 + k0 + 8);
                unsigned c0 = *(const unsigned*)(bsl + nn * 72 + k0);
                unsigned c1 = *(const unsigned*)(bsl + nn * 72 + k0 + 8);
#pragma unroll
                for (int mf = 0; mf < 2; mf++) {
                    MMA_ACC(acc[mf][nf], Ahi[mf], b0, b1);
                    MMA_ACC(acc[mf][nf], Alo[mf], b0, b1);
                    MMA_ACC(acc[mf][nf], Ahi[mf], c0, c1);
                }
            }
        }

#pragma unroll
        for (int mf = 0; mf < 2; mf++) {
            int r0 = m0 + wm + mf * 16 + r;
#pragma unroll
            for (int nf = 0; nf < 4; nf++) {
                int c = n0 + wn + nf * 8 + kq;
                if (r0 < M)
                    *(float2*)(C + (size_t)r0 * 192 + c) =
                        make_float2(acc[mf][nf][0], acc[mf][nf][1]);
                if (r0 + 8 < M)
                    *(float2*)(C + (size_t)(r0 + 8) * 192 + c) =
                        make_float2(acc[mf][nf][2], acc[mf][nf][3]);
            }
        }
    }
}

// ---------------- GRU gates (fp32) + optional fused final-step pool ----------------
__global__ void __launch_bounds__(256) k_gates(const float* __restrict__ bih,
                                               const float* __restrict__ bhh,
                                               const int* __restrict__ batch,
                                               const float* __restrict__ Wout,
                                               const float* __restrict__ bout,
                                               float* __restrict__ out,
                                               int final_) {
    int idx = blockIdx.x * 256 + threadIdx.x;
    if (idx >= NN * 64) return;
    int v = idx >> 6, j = idx & 63;
    const float* gi = g_gi + (size_t)v * 192;
    const float* gh = g_gh + (size_t)v * 192;
    float ir = gi[j] + bih[j],        iz = gi[64 + j] + bih[64 + j],  in_ = gi[128 + j] + bih[128 + j];
    float hr = gh[j] + bhh[j],        hz = gh[64 + j] + bhh[64 + j],  hn = gh[128 + j] + bhh[128 + j];
    float rr = 1.f / (1.f + expf(-(ir + hr)));
    float zz = 1.f / (1.f + expf(-(iz + hz)));
    float nn = tanhf(in_ + rr * hn);
    float h0 = g_x[idx];
    float hv = (1.f - zz) * nn + zz * h0;
    g_x[idx] = hv;
    if (final_) {
        // warp = 32 contiguous j of one node (NN*64 divisible by 256; all warps full)
        float p = hv * Wout[j];
#pragma unroll
        for (int o = 16; o; o >>= 1) p += __shfl_down_sync(0xffffffffu, p, o);
        if ((threadIdx.x & 31) == 0)
            atomicAdd(out + batch[v], p + ((j == 0) ? bout[0] : 0.f));
    }
}

// ---------------- launch ----------------
extern "C" void kernel_launch(void* const* d_in, const int* in_sizes, int n_in,
                              void* d_out, int out_size) {
    const float* nf    = (const float*)d_in[0];
    const float* ef    = (const float*)d_in[1];
    const int*   esrc  = (const int*)d_in[2];
    const int*   etgt  = (const int*)d_in[3];
    const int*   batch = (const int*)d_in[4];
    const float* Win   = (const float*)d_in[5];
    const float* bin   = (const float*)d_in[6];
    const float* We1   = (const float*)d_in[7];
    const float* be1   = (const float*)d_in[8];
    const float* We2   = (const float*)d_in[9];
    const float* be2   = (const float*)d_in[10];
    const float* Wih   = (const float*)d_in[11];
    const float* bih   = (const float*)d_in[12];
    const float* Whh   = (const float*)d_in[13];
    const float* bhh   = (const float*)d_in[14];
    const float* Wout  = (const float*)d_in[15];
    const float* bout  = (const float*)d_in[16];

    const int SM_GEMM = 2 * 128 * 72 * 2 + 2 * 64 * 72 * 2;
    cudaFuncSetAttribute(k_msg, cudaFuncAttributeMaxDynamicSharedMemorySize, MSG_SMEM);
    cudaFuncSetAttribute(gemm_gru, cudaFuncAttributeMaxDynamicSharedMemorySize, SM_GEMM);

    void *p_agg, *p_x;
    cudaGetSymbolAddress(&p_agg, g_agg);
    cudaGetSymbolAddress(&p_x, g_x);

    k_x0<<<(NN * 64 + 255) / 256, 256>>>(nf, Win, bin);
    k_edge_mlp<<<(NE + 63) / 64, 256>>>(ef, We1, be1);
    k_prep<<<(262144 + 24576 + 4096 + 255) / 256, 256>>>(We2, Wih, Whh, be2);
    cudaMemsetAsync(p_agg, 0, (size_t)NN * 64 * sizeof(float));  // step-0; later steps zeroed in gemm_gru
    cudaMemsetAsync(d_out, 0, (size_t)out_size * sizeof(float));

    for (int t = 0; t < 3; t++) {
        k_msg<<<(NE + 127) / 128, 256, MSG_SMEM>>>(esrc, etgt);
        gemm_gru<<<dim3((NN + 127) / 128, 2), 256, SM_GEMM>>>(
            (const float*)p_agg, (const float*)p_x);
        k_gates<<<(NN * 64 + 255) / 256, 256>>>(bih, bhh, batch, Wout, bout,
                                                (float*)d_out, t == 2 ? 1 : 0);
    }
}

// round 14
// speedup vs baseline: 1.1064x; 1.1064x over previous
#include <cuda_runtime.h>
#include <cuda_fp16.h>
#include <cstdint>

#define NN 50000
#define NE 100000

// ---------------- persistent device scratch ----------------
__device__ float  g_x[NN * 64];
__device__ float  g_agg[NN * 64];
__device__ float  g_ehT[(size_t)64 * NE];     // edge hidden, transposed [h][e]
__device__ __half g_b2h[64 * 4096];           // permuted We2 hi: [o][h*64+j]
__device__ __half g_b2l[64 * 4096];           // permuted We2 lo
__device__ __half g_bm_h[64 * 64];            // be2 as matrix, hi
__device__ __half g_bm_l[64 * 64];            // be2 as matrix, lo
__device__ __half g_wih_h[192 * 64];
__device__ __half g_wih_l[192 * 64];
__device__ __half g_whh_h[192 * 64];
__device__ __half g_whh_l[192 * 64];
__device__ float  g_gi[(size_t)NN * 192];
__device__ float  g_gh[(size_t)NN * 192];

__device__ __forceinline__ uint32_t smem_u32(const void* p) {
    uint32_t a;
    asm("{ .reg .u64 t; cvta.to.shared.u64 t, %1; cvt.u32.u64 %0, t; }" : "=r"(a) : "l"(p));
    return a;
}

#define MMA_ACC(d, a, b0, b1)                                             \
    asm volatile(                                                         \
        "mma.sync.aligned.m16n8k16.row.col.f32.f16.f16.f32 "              \
        "{%0,%1,%2,%3},{%4,%5,%6,%7},{%8,%9},{%0,%1,%2,%3};"              \
        : "+f"((d)[0]), "+f"((d)[1]), "+f"((d)[2]), "+f"((d)[3])          \
        : "r"((a)[0]), "r"((a)[1]), "r"((a)[2]), "r"((a)[3]),             \
          "r"(b0), "r"(b1))

#define MMA_NEW(d, a, b0, b1, z)                                          \
    asm volatile(                                                         \
        "mma.sync.aligned.m16n8k16.row.col.f32.f16.f16.f32 "              \
        "{%0,%1,%2,%3},{%4,%5,%6,%7},{%8,%9},{%10,%10,%10,%10};"          \
        : "=f"((d)[0]), "=f"((d)[1]), "=f"((d)[2]), "=f"((d)[3])          \
        : "r"((a)[0]), "r"((a)[1]), "r"((a)[2]), "r"((a)[3]),             \
          "r"(b0), "r"(b1), "f"(z))

#define LDSM4(r0, r1, r2, r3, addr)                                       \
    asm volatile("ldmatrix.sync.aligned.m8n8.x4.shared.b16 {%0,%1,%2,%3}, [%4];" \
        : "=r"(r0), "=r"(r1), "=r"(r2), "=r"(r3) : "r"(addr))

#define CP16(dst, src) \
    asm volatile("cp.async.cg.shared.global [%0], [%1], 16;" :: "r"(dst), "l"(src))
#define CPCOMMIT() asm volatile("cp.async.commit_group;")
#define CPWAIT0()  asm volatile("cp.async.wait_group 0;")

// ---------------- x0 = NF @ Win^T + bin (fp32) ----------------
__global__ void __launch_bounds__(256) k_x0(const float* __restrict__ nf,
                                            const float* __restrict__ Win,
                                            const float* __restrict__ bin) {
    __shared__ float w[1024];
    __shared__ float b[64];
    int tid = threadIdx.x;
    for (int i = tid; i < 1024; i += 256) w[i] = Win[i];
    if (tid < 64) b[tid] = bin[tid];
    __syncthreads();
    int idx = blockIdx.x * 256 + tid;
    if (idx >= NN * 64) return;
    int v = idx >> 6, h = idx & 63;
    const float* row = nf + (size_t)v * 16;
    float acc = b[h];
#pragma unroll
    for (int k = 0; k < 16; k++) acc += row[k] * w[h * 16 + k];
    g_x[idx] = acc;
}

// ---------------- eh = relu(EF @ We1^T + be1), stored transposed fp32 ----------------
__global__ void __launch_bounds__(256) k_edge_mlp(const float* __restrict__ ef,
                                                  const float* __restrict__ We1,
                                                  const float* __restrict__ be1) {
    __shared__ float w[512];
    __shared__ float b[64];
    __shared__ float efs[64 * 8];
    __shared__ float tile[64 * 65];
    int tid = threadIdx.x;
    for (int i = tid; i < 512; i += 256) w[i] = We1[i];
    if (tid < 64) b[tid] = be1[tid];
    int e0 = blockIdx.x * 64;
    for (int i = tid; i < 512; i += 256) {
        int el = i >> 3, k = i & 7;
        efs[i] = (e0 + el < NE) ? ef[(size_t)(e0 + el) * 8 + k] : 0.f;
    }
    __syncthreads();
#pragma unroll
    for (int t = 0; t < 16; t++) {
        int idx = tid + 256 * t;
        int el = idx >> 6, h = idx & 63;
        float acc = b[h];
#pragma unroll
        for (int k = 0; k < 8; k++) acc += efs[el * 8 + k] * w[h * 8 + k];
        tile[el * 65 + h] = fmaxf(acc, 0.f);
    }
    __syncthreads();
#pragma unroll
    for (int t = 0; t < 16; t++) {
        int idx = tid + 256 * t;
        int h = idx >> 6, el = idx & 63;
        if (e0 + el < NE) g_ehT[(size_t)h * NE + e0 + el] = tile[el * 65 + h];
    }
}

// ---------------- weight preparation: permute + hi/lo fp16 split ----------------
__global__ void __launch_bounds__(256) k_prep(const float* __restrict__ We2,
                                              const float* __restrict__ Wih,
                                              const float* __restrict__ Whh,
                                              const float* __restrict__ be2) {
    int i = blockIdx.x * 256 + threadIdx.x;
    if (i < 262144) {
        int o = i >> 12;
        int k = i & 4095;
        int h = k >> 6, j = k & 63;
        float v = We2[(size_t)(o * 64 + j) * 64 + h];
        __half hi = __float2half_rn(v);
        g_b2h[i] = hi;
        g_b2l[i] = __float2half_rn(v - __half2float(hi));
    } else if (i < 262144 + 12288) {
        int t = i - 262144;
        float v = Wih[t];
        __half hi = __float2half_rn(v);
        g_wih_h[t] = hi;
        g_wih_l[t] = __float2half_rn(v - __half2float(hi));
    } else if (i < 262144 + 24576) {
        int t = i - 274432;
        float v = Whh[t];
        __half hi = __float2half_rn(v);
        g_whh_h[t] = hi;
        g_whh_l[t] = __float2half_rn(v - __half2float(hi));
    } else if (i < 262144 + 24576 + 4096) {
        int t = i - 286720;
        float v = be2[t];
        __half hi = __float2half_rn(v);
        g_bm_h[t] = hi;
        g_bm_l[t] = __float2half_rn(v - __half2float(hi));
    }
}

// ---------------- fused message GEMM (X-invariant A, per-unit eh scaling) ----------------
// Round-9 proven configuration: 3-pass split, 2-buffer B pipe, barrier per unit,
// eh tile in SMEM. For each unit u: tmp = X_split @ B_u_split, acc += eh[row,u]*tmp.
// Unit 64 = be2-matrix with eh==1.
#define MSG_SMEM 108544

__global__ void __launch_bounds__(256) k_msg(const int* __restrict__ esrc,
                                             const int* __restrict__ etgt) {
    extern __shared__ char smc[];
    uint32_t base = smem_u32(smc);
    float* ehs = (float*)(smc + 73728);
    int*   sc  = (int*)(smc + 107520);
    int*   tg  = (int*)(smc + 108032);

    int tid = threadIdx.x, lane = tid & 31, wid = tid >> 5;
    int e0 = blockIdx.x * 128;
    int nEl = NE - e0; if (nEl > 128) nEl = 128;

#define COPY_B(v, d) do {                                                       \
        const __half* _sh; const __half* _sl; size_t _st;                       \
        if ((v) < 64) { _sh = g_b2h + (size_t)(v) * 64;                         \
                        _sl = g_b2l + (size_t)(v) * 64; _st = 4096; }           \
        else          { _sh = g_bm_h; _sl = g_bm_l; _st = 64; }                 \
        _Pragma("unroll")                                                       \
        for (int _i = 0; _i < 2; _i++) {                                        \
            int _id = tid + 256 * _i;                                           \
            int _row = _id >> 3, _q = _id & 7;                                  \
            uint32_t _dh = base + 36864 + (uint32_t)(d) * 9216 + _row * 144 + _q * 16; \
            CP16(_dh, _sh + (size_t)_row * _st + _q * 8);                       \
            CP16(_dh + 18432, _sl + (size_t)_row * _st + _q * 8);               \
        }                                                                       \
        CPCOMMIT();                                                             \
    } while (0)

    COPY_B(0, 0);   // prefetch unit 0 while we build X / eh tiles

    if (tid < 128) {
        sc[tid] = (tid < nEl) ? esrc[e0 + tid] : 0;
        tg[tid] = (tid < nEl) ? etgt[e0 + tid] : 0;
    }
    __syncthreads();

    __half* XH = (__half*)smc;
    __half* XL = (__half*)(smc + 18432);
#pragma unroll
    for (int i = 0; i < 32; i++) {
        int idx = tid + 256 * i;
        int row = idx >> 6, j = idx & 63;
        float v = g_x[(size_t)sc[row] * 64 + j];
        __half hi = __float2half_rn(v);
        XH[row * 72 + j] = hi;
        XL[row * 72 + j] = __float2half_rn(v - __half2float(hi));
    }
#pragma unroll
    for (int i = 0; i < 32; i++) {
        int idx = tid + 256 * i;
        int u = idx >> 7, e = idx & 127;
        float v = (e0 + e < NE) ? g_ehT[(size_t)u * NE + e0 + e] : 0.f;
        ehs[e * 66 + u] = v;
    }
    if (tid < 128) ehs[tid * 66 + 64] = 1.f;

    int wm = (wid >> 1) * 32, wn = (wid & 1) * 32;
    int r = lane >> 2, kq = (lane & 3) * 2;

    uint32_t aOff = (uint32_t)(wm + (lane & 15)) * 144 + (uint32_t)(lane >> 4) * 16;
    uint32_t aHiB = base + aOff;
    uint32_t bOff0 = (uint32_t)(wn + (lane & 7) + ((lane & 16) >> 1)) * 144 + ((uint32_t)(lane & 8) << 1);
    uint32_t bOff1 = bOff0 + 16 * 144;

    float acc[2][4][4];
#pragma unroll
    for (int a = 0; a < 2; a++)
#pragma unroll
        for (int b = 0; b < 4; b++)
#pragma unroll
            for (int c = 0; c < 4; c++) acc[a][b][c] = 0.f;

    float fz = 0.f;
    int ehbase0 = (wm + r) * 66;
    int ehbase1 = (wm + 16 + r) * 66;

    for (int u = 0; u <= 64; u++) {
        int b = u & 1;
        CPWAIT0();
        __syncthreads();
        if (u < 64) COPY_B(u + 1, b ^ 1);

        uint32_t bhB = base + 36864 + (uint32_t)b * 9216;

        float tmp[2][4][4];
#pragma unroll
        for (int kk = 0; kk < 4; kk++) {
            uint32_t ah[2][4], al[2][4], bh[2][4], bl[2][4];
#pragma unroll
            for (int mf = 0; mf < 2; mf++) {
                uint32_t aa = aHiB + (uint32_t)mf * 2304 + (uint32_t)kk * 32;
                LDSM4(ah[mf][0], ah[mf][1], ah[mf][2], ah[mf][3], aa);
                LDSM4(al[mf][0], al[mf][1], al[mf][2], al[mf][3], aa + 18432);
            }
            {
                uint32_t ba0 = bhB + bOff0 + (uint32_t)kk * 32;
                uint32_t ba1 = bhB + bOff1 + (uint32_t)kk * 32;
                LDSM4(bh[0][0], bh[0][1], bh[0][2], bh[0][3], ba0);
                LDSM4(bh[1][0], bh[1][1], bh[1][2], bh[1][3], ba1);
                LDSM4(bl[0][0], bl[0][1], bl[0][2], bl[0][3], ba0 + 18432);
                LDSM4(bl[1][0], bl[1][1], bl[1][2], bl[1][3], ba1 + 18432);
            }
#pragma unroll
            for (int nf = 0; nf < 4; nf++) {
                int np = nf >> 1, o = (nf & 1) * 2;
                uint32_t b0 = bh[np][o], b1 = bh[np][o + 1];
                uint32_t c0 = bl[np][o], c1 = bl[np][o + 1];
#pragma unroll
                for (int mf = 0; mf < 2; mf++) {
                    if (kk == 0) { MMA_NEW(tmp[mf][nf], ah[mf], b0, b1, fz); }
                    else         { MMA_ACC(tmp[mf][nf], ah[mf], b0, b1); }
                    MMA_ACC(tmp[mf][nf], al[mf], b0, b1);
                    MMA_ACC(tmp[mf][nf], ah[mf], c0, c1);
                }
            }
        }
        float e00 = ehs[ehbase0 + u], e01 = ehs[ehbase0 + 8 * 66 + u];
        float e10 = ehs[ehbase1 + u], e11 = ehs[ehbase1 + 8 * 66 + u];
#pragma unroll
        for (int nf = 0; nf < 4; nf++) {
            acc[0][nf][0] += e00 * tmp[0][nf][0];
            acc[0][nf][1] += e00 * tmp[0][nf][1];
            acc[0][nf][2] += e01 * tmp[0][nf][2];
            acc[0][nf][3] += e01 * tmp[0][nf][3];
            acc[1][nf][0] += e10 * tmp[1][nf][0];
            acc[1][nf][1] += e10 * tmp[1][nf][1];
            acc[1][nf][2] += e11 * tmp[1][nf][2];
            acc[1][nf][3] += e11 * tmp[1][nf][3];
        }
    }

#pragma unroll
    for (int mf = 0; mf < 2; mf++) {
        int rl = wm + mf * 16 + r;
#pragma unroll
        for (int nf = 0; nf < 4; nf++) {
            int c = wn + nf * 8 + kq;
            if (rl < nEl) {
                float* ap = g_agg + (size_t)tg[rl] * 64 + c;
                atomicAdd(ap,     acc[mf][nf][0]);
                atomicAdd(ap + 1, acc[mf][nf][1]);
            }
            if (rl + 8 < nEl) {
                float* ap = g_agg + (size_t)tg[rl + 8] * 64 + c;
                atomicAdd(ap,     acc[mf][nf][2]);
                atomicAdd(ap + 1, acc[mf][nf][3]);
            }
        }
    }
#undef COPY_B
}

// ---------------- fused GRU GEMM: y=0: gi=agg@Wih^T, y=1: gh=x@Whh^T (3-pass split) ----
__global__ void __launch_bounds__(256) gemm_gru(const float* __restrict__ Aagg,
                                                const float* __restrict__ Ax) {
    extern __shared__ char smc[];
    __half* ash = (__half*)smc;           // [128][72]
    __half* asl = ash + 128 * 72;
    __half* bsh = asl + 128 * 72;         // [64][72]
    __half* bsl = bsh + 64 * 72;

    const float* A   = blockIdx.y ? Ax : Aagg;
    const __half* BhAll = blockIdx.y ? g_whh_h : g_wih_h;
    const __half* BlAll = blockIdx.y ? g_whh_l : g_wih_l;
    float* C         = blockIdx.y ? g_gh : g_gi;

    int tid = threadIdx.x, lane = tid & 31, wid = tid >> 5;
    int m0 = blockIdx.x * 128;
    int M = NN;

#pragma unroll
    for (int i = 0; i < 32; i++) {
        int idx = tid + 256 * i;
        int rr = idx >> 6, j = idx & 63;
        float v = (m0 + rr < M) ? A[(size_t)(m0 + rr) * 64 + j] : 0.f;
        __half hi = __float2half_rn(v);
        ash[rr * 72 + j] = hi;
        asl[rr * 72 + j] = __float2half_rn(v - __half2float(hi));
    }

    int wm = (wid >> 1) * 32, wn = (wid & 1) * 32;
    int r = lane >> 2, kq = (lane & 3) * 2;

    for (int nc = 0; nc < 3; nc++) {
        int n0 = nc * 64;
        __syncthreads();
#pragma unroll
        for (int i = 0; i < 2; i++) {
            int id2 = tid + 256 * i;
            int row = id2 >> 3, q = id2 & 7;
            *(uint4*)(bsh + row * 72 + q * 8) = *(const uint4*)(BhAll + (size_t)(n0 + row) * 64 + q * 8);
            *(uint4*)(bsl + row * 72 + q * 8) = *(const uint4*)(BlAll + (size_t)(n0 + row) * 64 + q * 8);
        }
        __syncthreads();

        float acc[2][4][4];
#pragma unroll
        for (int a = 0; a < 2; a++)
#pragma unroll
            for (int b = 0; b < 4; b++)
#pragma unroll
                for (int c = 0; c < 4; c++) acc[a][b][c] = 0.f;

#pragma unroll
        for (int kk = 0; kk < 4; kk++) {
            int k0 = kk * 16 + kq;
            unsigned Ahi[2][4], Alo[2][4];
#pragma unroll
            for (int mf = 0; mf < 2; mf++) {
                int rr = wm + mf * 16 + r;
                Ahi[mf][0] = *(const unsigned*)(ash + rr * 72 + k0);
                Ahi[mf][1] = *(const unsigned*)(ash + (rr + 8) * 72 + k0);
                Ahi[mf][2] = *(const unsigned*)(ash + rr * 72 + k0 + 8);
                Ahi[mf][3] = *(const unsigned*)(ash + (rr + 8) * 72 + k0 + 8);
                Alo[mf][0] = *(const unsigned*)(asl + rr * 72 + k0);
                Alo[mf][1] = *(const unsigned*)(asl + (rr + 8) * 72 + k0);
                Alo[mf][2] = *(const unsigned*)(asl + rr * 72 + k0 + 8);
                Alo[mf][3] = *(const unsigned*)(asl + (rr + 8) * 72 + k0 + 8);
            }
#pragma unroll
            for (int nf = 0; nf < 4; nf++) {
                int nn = wn + nf * 8 + r;
                unsigned b0 = *(const unsigned*)(bsh + nn * 72 + k0);
                unsigned b1 = *(const unsigned*)(bsh + nn * 72 + k0 + 8);
                unsigned c0 = *(const unsigned*)(bsl + nn * 72 + k0);
                unsigned c1 = *(const unsigned*)(bsl + nn * 72 + k0 + 8);
#pragma unroll
                for (int mf = 0; mf < 2; mf++) {
                    MMA_ACC(acc[mf][nf], Ahi[mf], b0, b1);
                    MMA_ACC(acc[mf][nf], Alo[mf], b0, b1);
                    MMA_ACC(acc[mf][nf], Ahi[mf], c0, c1);
                }
            }
        }

#pragma unroll
        for (int mf = 0; mf < 2; mf++) {
            int r0 = m0 + wm + mf * 16 + r;
#pragma unroll
            for (int nf = 0; nf < 4; nf++) {
                int c = n0 + wn + nf * 8 + kq;
                if (r0 < M)
                    *(float2*)(C + (size_t)r0 * 192 + c) =
                        make_float2(acc[mf][nf][0], acc[mf][nf][1]);
                if (r0 + 8 < M)
                    *(float2*)(C + (size_t)(r0 + 8) * 192 + c) =
                        make_float2(acc[mf][nf][2], acc[mf][nf][3]);
            }
        }
    }
}

// ---------------- GRU gates (fp32, biases applied here) ----------------
__global__ void __launch_bounds__(256) k_gates(const float* __restrict__ bih,
                                               const float* __restrict__ bhh) {
    int idx = blockIdx.x * 256 + threadIdx.x;
    if (idx >= NN * 64) return;
    int v = idx >> 6, j = idx & 63;
    const float* gi = g_gi + (size_t)v * 192;
    const float* gh = g_gh + (size_t)v * 192;
    float ir = gi[j] + bih[j],        iz = gi[64 + j] + bih[64 + j],  in_ = gi[128 + j] + bih[128 + j];
    float hr = gh[j] + bhh[j],        hz = gh[64 + j] + bhh[64 + j],  hn = gh[128 + j] + bhh[128 + j];
    float rr = 1.f / (1.f + expf(-(ir + hr)));
    float zz = 1.f / (1.f + expf(-(iz + hz)));
    float nn = tanhf(in_ + rr * hn);
    float h0 = g_x[idx];
    g_x[idx] = (1.f - zz) * nn + zz * h0;
}

// ---------------- readout + pooled segment sum ----------------
__global__ void __launch_bounds__(256) k_pool(const int* __restrict__ batch,
                                              const float* __restrict__ Wout,
                                              const float* __restrict__ bout,
                                              float* __restrict__ out) {
    int lane = threadIdx.x & 31, wid = threadIdx.x >> 5;
    int v = blockIdx.x * 8 + wid;
    if (v >= NN) return;
    float w0 = Wout[lane], w1 = Wout[32 + lane];
    float p = g_x[(size_t)v * 64 + lane] * w0 + g_x[(size_t)v * 64 + 32 + lane] * w1;
#pragma unroll
    for (int o = 16; o; o >>= 1) p += __shfl_down_sync(0xffffffffu, p, o);
    if (lane == 0) atomicAdd(out + batch[v], p + bout[0]);
}

// ---------------- launch ----------------
extern "C" void kernel_launch(void* const* d_in, const int* in_sizes, int n_in,
                              void* d_out, int out_size) {
    const float* nf    = (const float*)d_in[0];
    const float* ef    = (const float*)d_in[1];
    const int*   esrc  = (const int*)d_in[2];
    const int*   etgt  = (const int*)d_in[3];
    const int*   batch = (const int*)d_in[4];
    const float* Win   = (const float*)d_in[5];
    const float* bin   = (const float*)d_in[6];
    const float* We1   = (const float*)d_in[7];
    const float* be1   = (const float*)d_in[8];
    const float* We2   = (const float*)d_in[9];
    const float* be2   = (const float*)d_in[10];
    const float* Wih   = (const float*)d_in[11];
    const float* bih   = (const float*)d_in[12];
    const float* Whh   = (const float*)d_in[13];
    const float* bhh   = (const float*)d_in[14];
    const float* Wout  = (const float*)d_in[15];
    const float* bout  = (const float*)d_in[16];

    const int SM_GEMM = 2 * 128 * 72 * 2 + 2 * 64 * 72 * 2;
    cudaFuncSetAttribute(k_msg, cudaFuncAttributeMaxDynamicSharedMemorySize, MSG_SMEM);
    cudaFuncSetAttribute(gemm_gru, cudaFuncAttributeMaxDynamicSharedMemorySize, SM_GEMM);

    void *p_agg, *p_x;
    cudaGetSymbolAddress(&p_agg, g_agg);
    cudaGetSymbolAddress(&p_x, g_x);

    k_x0<<<(NN * 64 + 255) / 256, 256>>>(nf, Win, bin);
    k_edge_mlp<<<(NE + 63) / 64, 256>>>(ef, We1, be1);
    k_prep<<<(262144 + 24576 + 4096 + 255) / 256, 256>>>(We2, Wih, Whh, be2);

    for (int t = 0; t < 3; t++) {
        cudaMemsetAsync(p_agg, 0, (size_t)NN * 64 * sizeof(float));
        k_msg<<<(NE + 127) / 128, 256, MSG_SMEM>>>(esrc, etgt);
        gemm_gru<<<dim3((NN + 127) / 128, 2), 256, SM_GEMM>>>(
            (const float*)p_agg, (const float*)p_x);
        k_gates<<<(NN * 64 + 255) / 256, 256>>>(bih, bhh);
    }

    cudaMemsetAsync(d_out, 0, (size_t)out_size * sizeof(float));
    k_pool<<<(NN + 7) / 8, 256>>>(batch, Wout, bout, (float*)d_out);
}